// round 16
// baseline (speedup 1.0000x reference)
#include <cuda_runtime.h>
#include <cuda_fp16.h>
#include <cstdint>
#include <cstddef>

// ============================================================================
// RNNEncoder: h_t = relu(x_t@Wx^T + h_{t-1}@Wh^T + b), 35 steps (fp16 mma.sync).
// Persistent kernel, R11-proven GEMM paths, plus overlapped x conversion via a
// two-pool scheduler in which every claimed ticket is immediately runnable:
//   conv pool : x fp32->fp16, 32 row-blocks/t (1120), atomicAdd (never waits)
//   z pool    : z_t = x_t@Wx^T + b, gated by release frontier (claim via CAS
//               only below z_released, advanced when conv_done[t]==32)
//   h chain   : h_t = relu(z_t + h_{t-1}@Wh^T), 256 fixed owner CTAs
// Grid = 296 CTAs (2/SM): 256 h-owners + 40 workers.
// ============================================================================

#define B_ROWS   4096
#define U_DIM    1024
#define T_STEPS  35
#define K_FULL   2048
#define XSTRIDE  (T_STEPS * U_DIM)
#define NCH      16                  // chunks per tile-GEMM (K=1024)
#define ROWB     144                 // 64 halves = 128B + 16B pad
#define A_TILE   (128 * ROWB)
#define W_TILE   (128 * ROWB)
#define STAGE    (A_TILE + W_TILE)   // 36864
#define PIPE     3
#define SMEM_TOT (PIPE * STAGE)      // 110592 (x2 CTAs = 221184)
#define NTILES   256
#define NCTA     296
#define ZTILES   (T_STEPS * NTILES)  // 8960
#define CONV_PER_T 32
#define CONVTOT  (T_STEPS * CONV_PER_T)  // 1120

// g_sync layout: [0]=z_ticket [1]=conv_ticket [2]=z_released
//                [8+t]=zdone [48+t]=hbar [88+t]=conv_done
#define SY_ZT   0
#define SY_CT   1
#define SY_ZREL 2
#define SY_ZDONE(t) (8 + (t))
#define SY_HBAR(t)  (48 + (t))
#define SY_CDONE(t) (88 + (t))
#define SY_SIZE 128

// ---------------------------------------------------------------------------
__device__ __half    g_x16[(size_t)B_ROWS * T_STEPS * U_DIM];
__device__ __half    g_w16[(size_t)U_DIM * K_FULL];
__device__ __half    g_h16[2][(size_t)B_ROWS * U_DIM];
__device__ float     g_z[(size_t)T_STEPS * B_ROWS * U_DIM];
__device__ unsigned  g_sync[SY_SIZE];

// ---------------------------------------------------------------------------
__device__ __forceinline__ uint32_t smem_u32(const void* p) {
    uint32_t a;
    asm("{ .reg .u64 t; cvta.to.shared.u64 t, %1; cvt.u32.u64 %0, t; }" : "=r"(a) : "l"(p));
    return a;
}
#define CP16(s, g) asm volatile("cp.async.cg.shared.global [%0], [%1], 16;\n" :: "r"(s), "l"(g) : "memory")
#define CP_COMMIT() asm volatile("cp.async.commit_group;\n" ::: "memory")
#define CP_WAIT(n)  asm volatile("cp.async.wait_group %0;\n" :: "n"(n) : "memory")

__device__ __forceinline__ void ldsm_x4(uint32_t& r0, uint32_t& r1, uint32_t& r2, uint32_t& r3,
                                        uint32_t addr) {
    asm volatile("ldmatrix.sync.aligned.m8n8.x4.shared.b16 {%0,%1,%2,%3}, [%4];"
                 : "=r"(r0), "=r"(r1), "=r"(r2), "=r"(r3) : "r"(addr));
}
__device__ __forceinline__ void mma_f16(float* c, const uint32_t* a, const uint32_t* b) {
    asm volatile(
        "mma.sync.aligned.m16n8k16.row.col.f32.f16.f16.f32 "
        "{%0,%1,%2,%3}, {%4,%5,%6,%7}, {%8,%9}, {%0,%1,%2,%3};"
        : "+f"(c[0]), "+f"(c[1]), "+f"(c[2]), "+f"(c[3])
        : "r"(a[0]), "r"(a[1]), "r"(a[2]), "r"(a[3]), "r"(b[0]), "r"(b[1]));
}

// ---------------------------------------------------------------------------
__device__ __forceinline__ void load_chunk16(
    uint32_t stage, int chunk, const __half* __restrict__ aBase, size_t aStride,
    const __half* __restrict__ wBase, int colBase, int tid)
{
    const int k0 = chunk * 64;
    #pragma unroll
    for (int it = 0; it < 8; it++) {
        const int i = tid + it * 128;
        const int r = i >> 3, c = i & 7;
        CP16(stage + (uint32_t)(r * ROWB + c * 16), aBase + (size_t)r * aStride + k0 + c * 8);
    }
    #pragma unroll
    for (int it = 0; it < 8; it++) {
        const int i = tid + it * 128;
        const int r = i >> 3, c = i & 7;
        CP16(stage + A_TILE + (uint32_t)(r * ROWB + c * 16),
             wBase + (size_t)(colBase + r) * K_FULL + k0 + c * 8);
    }
}

// 128x128 tile GEMM over K=1024 (16 chunks), accumulating into acc.
__device__ __forceinline__ void tile_gemm16(
    uint32_t sb, const __half* __restrict__ aBase, size_t aStride,
    const __half* __restrict__ wBase, int colBase,
    int tid, int lane, int warpM, int warpN, float acc[4][8][4])
{
    __syncthreads();   // protect smem stages from the previous tile's readers
    #pragma unroll
    for (int p = 0; p < PIPE - 1; p++) {
        load_chunk16(sb + p * STAGE, p, aBase, aStride, wBase, colBase, tid);
        CP_COMMIT();
    }
    const uint32_t aRowOff = (uint32_t)(lane & 15) * ROWB + (uint32_t)(lane >> 4) * 16;
    const uint32_t bRowOff = (uint32_t)((lane & 7) + ((lane >> 4) << 3)) * ROWB
                           + (uint32_t)((lane >> 3) & 1) * 16;
    for (int c = 0; c < NCH; c++) {
        CP_WAIT(1);
        __syncthreads();
        if (c + 2 < NCH)
            load_chunk16(sb + ((c + 2) % PIPE) * STAGE, c + 2, aBase, aStride, wBase, colBase, tid);
        CP_COMMIT();

        const uint32_t st = sb + (c % PIPE) * STAGE;
        uint32_t aF[2][4][4];
        #pragma unroll
        for (int mt = 0; mt < 4; mt++) {
            const uint32_t ao = (uint32_t)(warpM + mt * 16) * ROWB + aRowOff;
            ldsm_x4(aF[0][mt][0], aF[0][mt][1], aF[0][mt][2], aF[0][mt][3], st + ao);
        }
        #pragma unroll
        for (int s = 0; s < 4; s++) {
            const uint32_t ks = s * 32;
            uint32_t bH[4][4];
            #pragma unroll
            for (int q = 0; q < 4; q++) {
                const uint32_t bo = (uint32_t)(warpN + q * 16) * ROWB + bRowOff + ks;
                ldsm_x4(bH[q][0], bH[q][1], bH[q][2], bH[q][3], st + A_TILE + bo);
            }
            if (s < 3) {
                #pragma unroll
                for (int mt = 0; mt < 4; mt++) {
                    const uint32_t ao = (uint32_t)(warpM + mt * 16) * ROWB + aRowOff + ks + 32;
                    ldsm_x4(aF[(s + 1) & 1][mt][0], aF[(s + 1) & 1][mt][1],
                            aF[(s + 1) & 1][mt][2], aF[(s + 1) & 1][mt][3], st + ao);
                }
            }
            #pragma unroll
            for (int mt = 0; mt < 4; mt++)
                #pragma unroll
                for (int q = 0; q < 4; q++) {
                    mma_f16(acc[mt][2*q],   aF[s & 1][mt], &bH[q][0]);
                    mma_f16(acc[mt][2*q+1], aF[s & 1][mt], &bH[q][2]);
                }
        }
    }
}

// ---------------------------------------------------------------------------
// conv ticket: x fp32 -> fp16 for timestep t, row-block rb (128 rows x 1024)
__device__ __forceinline__ void do_conv_tile(
    int t, int rb, const float* __restrict__ x32, __half* __restrict__ x16, int tid)
{
    const size_t rowStart = (size_t)rb * 128;
    const float4* src = (const float4*)(x32 + rowStart * XSTRIDE + (size_t)t * U_DIM);
    __half2*      dst = (__half2*)(x16 + rowStart * XSTRIDE + (size_t)t * U_DIM);
    #pragma unroll 8
    for (int it = 0; it < 256; it++) {
        const int idx = it * 128 + tid;
        const int r = idx >> 8, c = idx & 255;
        const float4 v = src[(size_t)r * (XSTRIDE / 4) + c];
        const size_t d = (size_t)r * (XSTRIDE / 2) + c * 2;
        dst[d]     = __floats2half2_rn(v.x, v.y);
        dst[d + 1] = __floats2half2_rn(v.z, v.w);
    }
    __syncthreads();
    if (tid == 0) {
        __threadfence();
        const unsigned prev = atomicAdd(&g_sync[SY_CDONE(t)], 1u);
        if (prev == CONV_PER_T - 1)
            atomicMax(&g_sync[SY_ZREL], (unsigned)((t + 1) * NTILES));
    }
}

// z ticket: z(t,tile) = x_t @ Wx^T + b (fp32 store, no relu)
__device__ __forceinline__ void do_z_tile(
    uint32_t sb, unsigned zi,
    const __half* __restrict__ x16, const __half* __restrict__ w16,
    const float* __restrict__ bias, float* __restrict__ z,
    int tid, int lane, int warpM, int warpN)
{
    const int t    = (int)(zi >> 8);
    const int tile = (int)(zi & 255);
    const int rowBase = (tile >> 3) * 128;
    const int colBase = (tile & 7) * 128;

    __threadfence();   // acquire x16 writes (released via conv_done/z_released)

    float acc[4][8][4];
    #pragma unroll
    for (int i = 0; i < 4; i++)
        #pragma unroll
        for (int j = 0; j < 8; j++)
            #pragma unroll
            for (int q = 0; q < 4; q++) acc[i][j][q] = 0.0f;

    tile_gemm16(sb, x16 + (size_t)t * U_DIM + (size_t)rowBase * XSTRIDE, XSTRIDE,
                w16, colBase, tid, lane, warpM, warpN, acc);

    float* zt = z + (size_t)t * B_ROWS * U_DIM;
    #pragma unroll
    for (int mt = 0; mt < 4; mt++) {
        const int r0 = rowBase + warpM + mt * 16 + (lane >> 2);
        #pragma unroll
        for (int nt = 0; nt < 8; nt++) {
            const int col = colBase + warpN + nt * 8 + (lane & 3) * 2;
            const float2 bv = *(const float2*)(bias + col);
            *(float2*)(zt + (size_t)r0 * U_DIM + col) =
                make_float2(acc[mt][nt][0] + bv.x, acc[mt][nt][1] + bv.y);
            *(float2*)(zt + (size_t)(r0 + 8) * U_DIM + col) =
                make_float2(acc[mt][nt][2] + bv.x, acc[mt][nt][3] + bv.y);
        }
    }
    __syncthreads();
    if (tid == 0) { __threadfence(); atomicAdd(&g_sync[SY_ZDONE(t)], 1u); }
}

// try to claim a released z ticket: >=0 ticket, -1 none released, -2 exhausted
__device__ __forceinline__ int try_claim_z() {
    unsigned cur = *(volatile unsigned*)&g_sync[SY_ZT];
    if (cur >= ZTILES) return -2;
    unsigned rel = *(volatile unsigned*)&g_sync[SY_ZREL];
    while (cur < rel) {
        const unsigned prev = atomicCAS(&g_sync[SY_ZT], cur, cur + 1u);
        if (prev == cur) return (int)cur;
        cur = prev;
        if (cur >= ZTILES) return -2;
        rel = *(volatile unsigned*)&g_sync[SY_ZREL];
    }
    return -1;
}

// ---------------------------------------------------------------------------
__global__ __launch_bounds__(128, 2)
void rnn_persist(const float* __restrict__ x32, __half* __restrict__ x16,
                 const __half* __restrict__ w16,
                 __half* __restrict__ h16, const float* __restrict__ bias,
                 float* __restrict__ z, float* __restrict__ out)
{
    extern __shared__ char smem[];
    const uint32_t sb = smem_u32(smem);
    const int tid  = threadIdx.x;
    const int lane = tid & 31;
    const int warp = tid >> 5;
    const int warpM = (warp & 1) * 64;
    const int warpN = (warp >> 1) * 64;
    const size_t HSZ = (size_t)B_ROWS * U_DIM;

    __shared__ unsigned sh_kind, sh_idx;

    // -------- pure workers (CTAs 256..295): prefer conv, then z --------
    if (blockIdx.x >= NTILES) {
        bool convdead = false;   // only tid 0 uses
        while (true) {
            if (tid == 0) {
                unsigned kind = 3, idx = 0;
                if (!convdead) {
                    const unsigned c = atomicAdd(&g_sync[SY_CT], 1u);
                    if (c < CONVTOT) { kind = 1; idx = c; }
                    else convdead = true;
                }
                if (kind == 3) {
                    const int zt = try_claim_z();
                    if (zt >= 0)                    { kind = 2; idx = (unsigned)zt; }
                    else if (zt == -2 && convdead)  { kind = 0; }
                }
                sh_kind = kind; sh_idx = idx;
            }
            __syncthreads();
            const unsigned kind = sh_kind, idx = sh_idx;
            __syncthreads();
            if (kind == 0) return;
            if (kind == 1)      do_conv_tile((int)(idx >> 5), (int)(idx & 31), x32, x16, tid);
            else if (kind == 2) do_z_tile(sb, idx, x16, w16, bias, z, tid, lane, warpM, warpN);
            else { if (tid == 0) __nanosleep(300); __syncthreads(); }
        }
    }

    // -------- fixed h-owner CTAs (0..255): prefer z, then conv --------
    const int myTile  = blockIdx.x;
    const int rowBase = (myTile >> 3) * 128;
    const int colBase = (myTile & 7) * 128;

    for (int t = 0; t < T_STEPS; t++) {
        while (true) {
            if (tid == 0) {
                const bool ready =
                    (*(volatile unsigned*)&g_sync[SY_ZDONE(t)] >= NTILES) &&
                    (t == 0 || *(volatile unsigned*)&g_sync[SY_HBAR(t - 1)] >= NTILES);
                unsigned kind = 3, idx = 0;
                if (ready) kind = 0;
                else {
                    const int zt = try_claim_z();
                    if (zt >= 0) { kind = 2; idx = (unsigned)zt; }
                    else {
                        const unsigned c = atomicAdd(&g_sync[SY_CT], 1u);
                        if (c < CONVTOT) { kind = 1; idx = c; }
                    }
                }
                sh_kind = kind; sh_idx = idx;
            }
            __syncthreads();
            const unsigned kind = sh_kind, idx = sh_idx;
            __syncthreads();
            if (kind == 0) break;
            if (kind == 1)      do_conv_tile((int)(idx >> 5), (int)(idx & 31), x32, x16, tid);
            else if (kind == 2) do_z_tile(sb, idx, x16, w16, bias, z, tid, lane, warpM, warpN);
            else { if (tid == 0) __nanosleep(400); __syncthreads(); }
        }
        __threadfence();   // acquire: z(t) and h(t-1) writes visible

        const __half* hprev = h16 + (size_t)(t & 1) * HSZ;
        __half*       hout  = h16 + (size_t)((t + 1) & 1) * HSZ;
        const float*  zt    = z + (size_t)t * B_ROWS * U_DIM;

        if (t == 0) {
            // h0 = relu(z0) elementwise
            #pragma unroll
            for (int mt = 0; mt < 4; mt++) {
                const int r0 = rowBase + warpM + mt * 16 + (lane >> 2);
                #pragma unroll
                for (int nt = 0; nt < 8; nt++) {
                    const int col = colBase + warpN + nt * 8 + (lane & 3) * 2;
                    const float2 a  = *(const float2*)(zt + (size_t)r0 * U_DIM + col);
                    const float2 b2 = *(const float2*)(zt + (size_t)(r0 + 8) * U_DIM + col);
                    *(__half2*)(hout + (size_t)r0 * U_DIM + col) =
                        __floats2half2_rn(a.x > 0.f ? a.x : 0.f, a.y > 0.f ? a.y : 0.f);
                    *(__half2*)(hout + (size_t)(r0 + 8) * U_DIM + col) =
                        __floats2half2_rn(b2.x > 0.f ? b2.x : 0.f, b2.y > 0.f ? b2.y : 0.f);
                }
            }
        } else {
            float acc[4][8][4];
            #pragma unroll
            for (int mt = 0; mt < 4; mt++) {
                const int r0 = rowBase + warpM + mt * 16 + (lane >> 2);
                #pragma unroll
                for (int nt = 0; nt < 8; nt++) {
                    const int col = colBase + warpN + nt * 8 + (lane & 3) * 2;
                    const float2 a  = *(const float2*)(zt + (size_t)r0 * U_DIM + col);
                    const float2 b2 = *(const float2*)(zt + (size_t)(r0 + 8) * U_DIM + col);
                    acc[mt][nt][0] = a.x;  acc[mt][nt][1] = a.y;
                    acc[mt][nt][2] = b2.x; acc[mt][nt][3] = b2.y;
                }
            }
            tile_gemm16(sb, hprev + (size_t)rowBase * U_DIM, U_DIM,
                        w16 + U_DIM, colBase, tid, lane, warpM, warpN, acc);

            const int writeF = (t == T_STEPS - 1);
            #pragma unroll
            for (int mt = 0; mt < 4; mt++) {
                const int r0 = rowBase + warpM + mt * 16 + (lane >> 2);
                #pragma unroll
                for (int nt = 0; nt < 8; nt++) {
                    const int col = colBase + warpN + nt * 8 + (lane & 3) * 2;
                    float v0 = acc[mt][nt][0]; v0 = v0 > 0.f ? v0 : 0.f;
                    float v1 = acc[mt][nt][1]; v1 = v1 > 0.f ? v1 : 0.f;
                    float v2 = acc[mt][nt][2]; v2 = v2 > 0.f ? v2 : 0.f;
                    float v3 = acc[mt][nt][3]; v3 = v3 > 0.f ? v3 : 0.f;
                    const size_t o0 = (size_t)r0 * U_DIM + col;
                    const size_t o1 = o0 + 8 * U_DIM;
                    if (writeF) {
                        *(float2*)(out + o0) = make_float2(v0, v1);
                        *(float2*)(out + o1) = make_float2(v2, v3);
                    } else {
                        *(__half2*)(hout + o0) = __floats2half2_rn(v0, v1);
                        *(__half2*)(hout + o1) = __floats2half2_rn(v2, v3);
                    }
                }
            }
        }
        __syncthreads();
        if (tid == 0) { __threadfence(); atomicAdd(&g_sync[SY_HBAR(t)], 1u); }
    }
}

// ---------------------------------------------------------------------------
__global__ void conv_f16_kernel(const float4* __restrict__ src,
                                __half2* __restrict__ dst, size_t n4)
{
    size_t i = (size_t)blockIdx.x * blockDim.x + threadIdx.x;
    if (i >= n4) return;
    float4 v = src[i];
    dst[2*i]   = __floats2half2_rn(v.x, v.y);
    dst[2*i+1] = __floats2half2_rn(v.z, v.w);
}

// ---------------------------------------------------------------------------
extern "C" void kernel_launch(void* const* d_in, const int* in_sizes, int n_in,
                              void* d_out, int out_size)
{
    const float* x = (const float*)d_in[0];
    const float* W = (const float*)d_in[1];
    const float* b = (const float*)d_in[2];
    float* out = (float*)d_out;

    __half *x16, *w16, *h16;
    float *z;
    unsigned* syncp;
    cudaGetSymbolAddress((void**)&x16, g_x16);
    cudaGetSymbolAddress((void**)&w16, g_w16);
    cudaGetSymbolAddress((void**)&h16, g_h16);
    cudaGetSymbolAddress((void**)&z,   g_z);
    cudaGetSymbolAddress((void**)&syncp, g_sync);

    static bool attr_set = false;
    if (!attr_set) {
        cudaFuncSetAttribute(rnn_persist, cudaFuncAttributeMaxDynamicSharedMemorySize, SMEM_TOT);
        attr_set = true;
    }

    // reset sync state (graph-replay safe)
    cudaMemsetAsync(syncp, 0, SY_SIZE * sizeof(unsigned));

    // W fp32 -> fp16 (12MB, ~6us; stays a pre-kernel)
    {
        size_t nW4 = (size_t)U_DIM * K_FULL / 4;
        conv_f16_kernel<<<(unsigned)((nW4 + 255) / 256), 256>>>(
            (const float4*)W, (__half2*)w16, nW4);
    }

    rnn_persist<<<NCTA, 128, SMEM_TOT>>>(x, x16, w16, h16, b, z, out);
}

// round 17
// speedup vs baseline: 3.6797x; 3.6797x over previous
#include <cuda_runtime.h>
#include <cuda_fp16.h>
#include <cstdint>
#include <cstddef>

// ============================================================================
// RNNEncoder: h_t = relu(x_t@Wx^T + h_{t-1}@Wh^T + b), 35 steps (fp16 mma.sync).
// Persistent kernel (R11 base) with EXACT dependency tracking:
//   z pool  : z_t = x_t@Wx^T + b; 256 tiles/t, unordered atomicAdd pool;
//             completion -> per-tile flag zflag[t*256+tile]
//   h chain : h_t[rb,cb] = relu(z_t[rb,cb] + h_{t-1}[rb,:]@Wh[cb,:])
//             deps: own zflag + hgroup[t-1][rb]==8  (32 independent row-group
//             chains instead of one global per-step barrier)
// Grid = 296 CTAs (2/SM): 256 fixed h-owners (fill waits with z) + 40 z-workers.
// x fp32->fp16 conversion is an upfront kernel (R11-proven; overlap attempts
// R13/R14/R16 all regressed).
// ============================================================================

#define B_ROWS   4096
#define U_DIM    1024
#define T_STEPS  35
#define K_FULL   2048
#define XSTRIDE  (T_STEPS * U_DIM)
#define NCH      16                  // chunks per tile-GEMM (K=1024)
#define ROWB     144                 // 64 halves = 128B + 16B pad
#define A_TILE   (128 * ROWB)
#define W_TILE   (128 * ROWB)
#define STAGE    (A_TILE + W_TILE)   // 36864
#define PIPE     3
#define SMEM_TOT (PIPE * STAGE)      // 110592 (x2 CTAs = 221184)
#define NTILES   256
#define NCTA     296
#define ZTILES   (T_STEPS * NTILES)  // 8960

// g_sync layout: [0]=z ticket; [64 + i]=zflag (i<8960); [9088 + t*32 + rg]=hgroup
#define SY_ZT       0
#define SY_ZFLAG(i) (64 + (i))
#define SY_HG(t,rg) (9088 + (t) * 32 + (rg))
#define SY_SIZE     10240

// ---------------------------------------------------------------------------
__device__ __half    g_x16[(size_t)B_ROWS * T_STEPS * U_DIM];
__device__ __half    g_w16[(size_t)U_DIM * K_FULL];
__device__ __half    g_h16[2][(size_t)B_ROWS * U_DIM];
__device__ float     g_z[(size_t)T_STEPS * B_ROWS * U_DIM];
__device__ unsigned  g_sync[SY_SIZE];

// ---------------------------------------------------------------------------
__device__ __forceinline__ uint32_t smem_u32(const void* p) {
    uint32_t a;
    asm("{ .reg .u64 t; cvta.to.shared.u64 t, %1; cvt.u32.u64 %0, t; }" : "=r"(a) : "l"(p));
    return a;
}
#define CP16(s, g) asm volatile("cp.async.cg.shared.global [%0], [%1], 16;\n" :: "r"(s), "l"(g) : "memory")
#define CP_COMMIT() asm volatile("cp.async.commit_group;\n" ::: "memory")
#define CP_WAIT(n)  asm volatile("cp.async.wait_group %0;\n" :: "n"(n) : "memory")

__device__ __forceinline__ void ldsm_x4(uint32_t& r0, uint32_t& r1, uint32_t& r2, uint32_t& r3,
                                        uint32_t addr) {
    asm volatile("ldmatrix.sync.aligned.m8n8.x4.shared.b16 {%0,%1,%2,%3}, [%4];"
                 : "=r"(r0), "=r"(r1), "=r"(r2), "=r"(r3) : "r"(addr));
}
__device__ __forceinline__ void mma_f16(float* c, const uint32_t* a, const uint32_t* b) {
    asm volatile(
        "mma.sync.aligned.m16n8k16.row.col.f32.f16.f16.f32 "
        "{%0,%1,%2,%3}, {%4,%5,%6,%7}, {%8,%9}, {%0,%1,%2,%3};"
        : "+f"(c[0]), "+f"(c[1]), "+f"(c[2]), "+f"(c[3])
        : "r"(a[0]), "r"(a[1]), "r"(a[2]), "r"(a[3]), "r"(b[0]), "r"(b[1]));
}

// ---------------------------------------------------------------------------
__device__ __forceinline__ void load_chunk16(
    uint32_t stage, int chunk, const __half* __restrict__ aBase, size_t aStride,
    const __half* __restrict__ wBase, int colBase, int tid)
{
    const int k0 = chunk * 64;
    #pragma unroll
    for (int it = 0; it < 8; it++) {
        const int i = tid + it * 128;
        const int r = i >> 3, c = i & 7;
        CP16(stage + (uint32_t)(r * ROWB + c * 16), aBase + (size_t)r * aStride + k0 + c * 8);
    }
    #pragma unroll
    for (int it = 0; it < 8; it++) {
        const int i = tid + it * 128;
        const int r = i >> 3, c = i & 7;
        CP16(stage + A_TILE + (uint32_t)(r * ROWB + c * 16),
             wBase + (size_t)(colBase + r) * K_FULL + k0 + c * 8);
    }
}

// 128x128 tile GEMM over K=1024 (16 chunks), accumulating into acc.
__device__ __forceinline__ void tile_gemm16(
    uint32_t sb, const __half* __restrict__ aBase, size_t aStride,
    const __half* __restrict__ wBase, int colBase,
    int tid, int lane, int warpM, int warpN, float acc[4][8][4])
{
    __syncthreads();   // protect smem stages from the previous tile's readers
    #pragma unroll
    for (int p = 0; p < PIPE - 1; p++) {
        load_chunk16(sb + p * STAGE, p, aBase, aStride, wBase, colBase, tid);
        CP_COMMIT();
    }
    const uint32_t aRowOff = (uint32_t)(lane & 15) * ROWB + (uint32_t)(lane >> 4) * 16;
    const uint32_t bRowOff = (uint32_t)((lane & 7) + ((lane >> 4) << 3)) * ROWB
                           + (uint32_t)((lane >> 3) & 1) * 16;
    for (int c = 0; c < NCH; c++) {
        CP_WAIT(1);
        __syncthreads();
        if (c + 2 < NCH)
            load_chunk16(sb + ((c + 2) % PIPE) * STAGE, c + 2, aBase, aStride, wBase, colBase, tid);
        CP_COMMIT();

        const uint32_t st = sb + (c % PIPE) * STAGE;
        uint32_t aF[2][4][4];
        #pragma unroll
        for (int mt = 0; mt < 4; mt++) {
            const uint32_t ao = (uint32_t)(warpM + mt * 16) * ROWB + aRowOff;
            ldsm_x4(aF[0][mt][0], aF[0][mt][1], aF[0][mt][2], aF[0][mt][3], st + ao);
        }
        #pragma unroll
        for (int s = 0; s < 4; s++) {
            const uint32_t ks = s * 32;
            uint32_t bH[4][4];
            #pragma unroll
            for (int q = 0; q < 4; q++) {
                const uint32_t bo = (uint32_t)(warpN + q * 16) * ROWB + bRowOff + ks;
                ldsm_x4(bH[q][0], bH[q][1], bH[q][2], bH[q][3], st + A_TILE + bo);
            }
            if (s < 3) {
                #pragma unroll
                for (int mt = 0; mt < 4; mt++) {
                    const uint32_t ao = (uint32_t)(warpM + mt * 16) * ROWB + aRowOff + ks + 32;
                    ldsm_x4(aF[(s + 1) & 1][mt][0], aF[(s + 1) & 1][mt][1],
                            aF[(s + 1) & 1][mt][2], aF[(s + 1) & 1][mt][3], st + ao);
                }
            }
            #pragma unroll
            for (int mt = 0; mt < 4; mt++)
                #pragma unroll
                for (int q = 0; q < 4; q++) {
                    mma_f16(acc[mt][2*q],   aF[s & 1][mt], &bH[q][0]);
                    mma_f16(acc[mt][2*q+1], aF[s & 1][mt], &bH[q][2]);
                }
        }
    }
}

// ---------------------------------------------------------------------------
// z ticket: z(t,tile) = x_t @ Wx^T + b (fp32 store, no relu), then per-tile flag
__device__ __forceinline__ void do_z_tile(
    uint32_t sb, unsigned zi,
    const __half* __restrict__ x16, const __half* __restrict__ w16,
    const float* __restrict__ bias, float* __restrict__ z,
    int tid, int lane, int warpM, int warpN)
{
    const int t    = (int)(zi >> 8);
    const int tile = (int)(zi & 255);
    const int rowBase = (tile >> 3) * 128;
    const int colBase = (tile & 7) * 128;

    float acc[4][8][4];
    #pragma unroll
    for (int i = 0; i < 4; i++)
        #pragma unroll
        for (int j = 0; j < 8; j++)
            #pragma unroll
            for (int q = 0; q < 4; q++) acc[i][j][q] = 0.0f;

    tile_gemm16(sb, x16 + (size_t)t * U_DIM + (size_t)rowBase * XSTRIDE, XSTRIDE,
                w16, colBase, tid, lane, warpM, warpN, acc);

    float* zt = z + (size_t)t * B_ROWS * U_DIM;
    #pragma unroll
    for (int mt = 0; mt < 4; mt++) {
        const int r0 = rowBase + warpM + mt * 16 + (lane >> 2);
        #pragma unroll
        for (int nt = 0; nt < 8; nt++) {
            const int col = colBase + warpN + nt * 8 + (lane & 3) * 2;
            const float2 bv = *(const float2*)(bias + col);
            *(float2*)(zt + (size_t)r0 * U_DIM + col) =
                make_float2(acc[mt][nt][0] + bv.x, acc[mt][nt][1] + bv.y);
            *(float2*)(zt + (size_t)(r0 + 8) * U_DIM + col) =
                make_float2(acc[mt][nt][2] + bv.x, acc[mt][nt][3] + bv.y);
        }
    }
    __syncthreads();
    if (tid == 0) { __threadfence(); atomicExch(&g_sync[SY_ZFLAG(zi)], 1u); }
}

// ---------------------------------------------------------------------------
__global__ __launch_bounds__(128, 2)
void rnn_persist(const __half* __restrict__ x16, const __half* __restrict__ w16,
                 __half* __restrict__ h16, const float* __restrict__ bias,
                 float* __restrict__ z, float* __restrict__ out)
{
    extern __shared__ char smem[];
    const uint32_t sb = smem_u32(smem);
    const int tid  = threadIdx.x;
    const int lane = tid & 31;
    const int warp = tid >> 5;
    const int warpM = (warp & 1) * 64;
    const int warpN = (warp >> 1) * 64;
    const size_t HSZ = (size_t)B_ROWS * U_DIM;

    __shared__ unsigned sh_work;

    // -------- pure z-workers (CTAs 256..295) --------
    if (blockIdx.x >= NTILES) {
        while (true) {
            if (tid == 0) sh_work = atomicAdd(&g_sync[SY_ZT], 1u);
            __syncthreads();
            const unsigned zi = sh_work;
            __syncthreads();
            if (zi >= ZTILES) return;
            do_z_tile(sb, zi, x16, w16, bias, z, tid, lane, warpM, warpN);
        }
    }

    // -------- fixed h-owner CTAs (0..255) --------
    const int myTile  = blockIdx.x;
    const int rg      = myTile >> 3;         // row group 0..31
    const int rowBase = rg * 128;
    const int colBase = (myTile & 7) * 128;
    bool pooldead = false;

    for (int t = 0; t < T_STEPS; t++) {
        // exact deps: own z tile flag + row-group h(t-1) count; fill with z work
        while (true) {
            if (tid == 0) {
                const bool ready =
                    (*(volatile unsigned*)&g_sync[SY_ZFLAG(t * NTILES + myTile)] != 0u) &&
                    (t == 0 || *(volatile unsigned*)&g_sync[SY_HG(t - 1, rg)] >= 8u);
                if (ready)          sh_work = 0xFFFFFFFFu;
                else if (!pooldead) sh_work = atomicAdd(&g_sync[SY_ZT], 1u);
                else                sh_work = 0xFFFFFFFEu;
            }
            __syncthreads();
            const unsigned w = sh_work;
            __syncthreads();
            if (w == 0xFFFFFFFFu) break;
            if (w < ZTILES) {
                do_z_tile(sb, w, x16, w16, bias, z, tid, lane, warpM, warpN);
            } else {
                pooldead = true;
                if (tid == 0) __nanosleep(400);
                __syncthreads();
            }
        }
        __threadfence();   // acquire: z tile and h(t-1) row-group writes visible

        const __half* hprev = h16 + (size_t)(t & 1) * HSZ;
        __half*       hout  = h16 + (size_t)((t + 1) & 1) * HSZ;
        const float*  zt    = z + (size_t)t * B_ROWS * U_DIM;

        if (t == 0) {
            // h0 = relu(z0) elementwise
            #pragma unroll
            for (int mt = 0; mt < 4; mt++) {
                const int r0 = rowBase + warpM + mt * 16 + (lane >> 2);
                #pragma unroll
                for (int nt = 0; nt < 8; nt++) {
                    const int col = colBase + warpN + nt * 8 + (lane & 3) * 2;
                    const float2 a  = *(const float2*)(zt + (size_t)r0 * U_DIM + col);
                    const float2 b2 = *(const float2*)(zt + (size_t)(r0 + 8) * U_DIM + col);
                    *(__half2*)(hout + (size_t)r0 * U_DIM + col) =
                        __floats2half2_rn(a.x > 0.f ? a.x : 0.f, a.y > 0.f ? a.y : 0.f);
                    *(__half2*)(hout + (size_t)(r0 + 8) * U_DIM + col) =
                        __floats2half2_rn(b2.x > 0.f ? b2.x : 0.f, b2.y > 0.f ? b2.y : 0.f);
                }
            }
        } else {
            float acc[4][8][4];
            #pragma unroll
            for (int mt = 0; mt < 4; mt++) {
                const int r0 = rowBase + warpM + mt * 16 + (lane >> 2);
                #pragma unroll
                for (int nt = 0; nt < 8; nt++) {
                    const int col = colBase + warpN + nt * 8 + (lane & 3) * 2;
                    const float2 a  = *(const float2*)(zt + (size_t)r0 * U_DIM + col);
                    const float2 b2 = *(const float2*)(zt + (size_t)(r0 + 8) * U_DIM + col);
                    acc[mt][nt][0] = a.x;  acc[mt][nt][1] = a.y;
                    acc[mt][nt][2] = b2.x; acc[mt][nt][3] = b2.y;
                }
            }
            tile_gemm16(sb, hprev + (size_t)rowBase * U_DIM, U_DIM,
                        w16 + U_DIM, colBase, tid, lane, warpM, warpN, acc);

            const int writeF = (t == T_STEPS - 1);
            #pragma unroll
            for (int mt = 0; mt < 4; mt++) {
                const int r0 = rowBase + warpM + mt * 16 + (lane >> 2);
                #pragma unroll
                for (int nt = 0; nt < 8; nt++) {
                    const int col = colBase + warpN + nt * 8 + (lane & 3) * 2;
                    float v0 = acc[mt][nt][0]; v0 = v0 > 0.f ? v0 : 0.f;
                    float v1 = acc[mt][nt][1]; v1 = v1 > 0.f ? v1 : 0.f;
                    float v2 = acc[mt][nt][2]; v2 = v2 > 0.f ? v2 : 0.f;
                    float v3 = acc[mt][nt][3]; v3 = v3 > 0.f ? v3 : 0.f;
                    const size_t o0 = (size_t)r0 * U_DIM + col;
                    const size_t o1 = o0 + 8 * U_DIM;
                    if (writeF) {
                        *(float2*)(out + o0) = make_float2(v0, v1);
                        *(float2*)(out + o1) = make_float2(v2, v3);
                    } else {
                        *(__half2*)(hout + o0) = __floats2half2_rn(v0, v1);
                        *(__half2*)(hout + o1) = __floats2half2_rn(v2, v3);
                    }
                }
            }
        }
        __syncthreads();
        if (tid == 0) { __threadfence(); atomicAdd(&g_sync[SY_HG(t, rg)], 1u); }
    }
}

// ---------------------------------------------------------------------------
__global__ void conv_f16_kernel(const float4* __restrict__ src,
                                __half2* __restrict__ dst, size_t n4)
{
    size_t i = (size_t)blockIdx.x * blockDim.x + threadIdx.x;
    if (i >= n4) return;
    float4 v = src[i];
    dst[2*i]   = __floats2half2_rn(v.x, v.y);
    dst[2*i+1] = __floats2half2_rn(v.z, v.w);
}

// ---------------------------------------------------------------------------
extern "C" void kernel_launch(void* const* d_in, const int* in_sizes, int n_in,
                              void* d_out, int out_size)
{
    const float* x = (const float*)d_in[0];
    const float* W = (const float*)d_in[1];
    const float* b = (const float*)d_in[2];
    float* out = (float*)d_out;

    __half *x16, *w16, *h16;
    float *z;
    unsigned* syncp;
    cudaGetSymbolAddress((void**)&x16, g_x16);
    cudaGetSymbolAddress((void**)&w16, g_w16);
    cudaGetSymbolAddress((void**)&h16, g_h16);
    cudaGetSymbolAddress((void**)&z,   g_z);
    cudaGetSymbolAddress((void**)&syncp, g_sync);

    static bool attr_set = false;
    if (!attr_set) {
        cudaFuncSetAttribute(rnn_persist, cudaFuncAttributeMaxDynamicSharedMemorySize, SMEM_TOT);
        attr_set = true;
    }

    // reset sync state (graph-replay safe)
    cudaMemsetAsync(syncp, 0, SY_SIZE * sizeof(unsigned));

    // fp32 -> fp16 conversions (upfront; R11-proven)
    {
        size_t nW4 = (size_t)U_DIM * K_FULL / 4;
        conv_f16_kernel<<<(unsigned)((nW4 + 255) / 256), 256>>>(
            (const float4*)W, (__half2*)w16, nW4);
        size_t nX4 = (size_t)B_ROWS * T_STEPS * U_DIM / 4;
        conv_f16_kernel<<<(unsigned)((nX4 + 255) / 256), 256>>>(
            (const float4*)x, (__half2*)x16, nX4);
    }

    rnn_persist<<<NCTA, 128, SMEM_TOT>>>(x16, w16, h16, b, z, out);
}